// round 1
// baseline (speedup 1.0000x reference)
#include <cuda_runtime.h>
#include <cstdint>

#define NN 3072
#define HH 64
#define VV 4
#define FULLMASK 0xFFFFFFFFu
#define NEGBIG (-1e30f)

// ------------------- scratch (device globals; no allocations) -------------------
__device__ float g_Wh[NN * HH];
__device__ float g_el[NN];
__device__ float g_er[NN];
__device__ float g_hgat[VV * NN * HH];
__device__ float g_q[VV * NN * HH];
__device__ float g_k[VV * NN * HH];
__device__ float g_v[VV * NN * HH];
__device__ float g_vals[VV * NN * HH];

__device__ __forceinline__ uint32_t f2tf(float f) {
    uint32_t u;
    asm("cvt.rna.tf32.f32 %0, %1;" : "=r"(u) : "f"(f));
    return u;
}

__device__ __forceinline__ void mma_tf32(float* d, const uint32_t* a, uint32_t b0, uint32_t b1) {
    asm volatile(
        "mma.sync.aligned.m16n8k8.row.col.f32.tf32.tf32.f32 "
        "{%0,%1,%2,%3}, {%4,%5,%6,%7}, {%8,%9}, {%0,%1,%2,%3};"
        : "+f"(d[0]), "+f"(d[1]), "+f"(d[2]), "+f"(d[3])
        : "r"(a[0]), "r"(a[1]), "r"(a[2]), "r"(a[3]), "r"(b0), "r"(b1));
}

// ------------------- K1: Wh = X @ W ; el = Wh@a[:H] ; er = Wh@a[H:] -------------------
__global__ void k1_wh(const float* __restrict__ x, const float* __restrict__ W,
                      const float* __restrict__ a) {
    __shared__ float Wsm[64 * 64];
    __shared__ float a_sm[128];
    int tid = threadIdx.x;
    for (int i = tid; i < 64 * 64; i += 256) Wsm[i] = W[i];
    if (tid < 128) a_sm[tid] = a[tid];
    __syncthreads();
    int warp = tid >> 5, lane = tid & 31;
    int row = blockIdx.x * 8 + warp;
    const float* xr = x + row * 64;
    float x0 = xr[lane], x1 = xr[lane + 32];
    float wh0 = 0.f, wh1 = 0.f;
#pragma unroll
    for (int k = 0; k < 64; k++) {
        float xk = __shfl_sync(FULLMASK, (k < 32) ? x0 : x1, k & 31);
        wh0 += xk * Wsm[k * 64 + lane];
        wh1 += xk * Wsm[k * 64 + lane + 32];
    }
    g_Wh[row * 64 + lane] = wh0;
    g_Wh[row * 64 + lane + 32] = wh1;
    float pl = wh0 * a_sm[lane] + wh1 * a_sm[lane + 32];
    float pr = wh0 * a_sm[64 + lane] + wh1 * a_sm[96 + lane];
#pragma unroll
    for (int o = 16; o; o >>= 1) {
        pl += __shfl_xor_sync(FULLMASK, pl, o);
        pr += __shfl_xor_sync(FULLMASK, pr, o);
    }
    if (lane == 0) { g_el[row] = pl; g_er[row] = pr; }
}

// ------------------- K2: GAT fused masked-softmax + SpMM (warp per (v,row)) -------------------
__global__ void __launch_bounds__(256) k2_gat(const float* __restrict__ adj) {
    __shared__ float er_s[NN];
    int tid = threadIdx.x;
    for (int i = tid; i < NN; i += 256) er_s[i] = g_er[i];
    __syncthreads();
    int gw = blockIdx.x * 8 + (tid >> 5);
    int lane = tid & 31;
    int v = gw / NN, row = gw - v * NN;
    const float4* adjrow = (const float4*)(adj + ((size_t)v * NN + row) * NN);
    const float4* er4p = (const float4*)er_s;
    float el = g_el[row];
    float m = NEGBIG, Z = 0.f;
    float4 acc[16];
#pragma unroll
    for (int h = 0; h < 16; h++) acc[h] = make_float4(0.f, 0.f, 0.f, 0.f);

    for (int jb = lane; jb < NN / 4; jb += 32) {
        float4 av = __ldcs(adjrow + jb);
        float4 er4 = er4p[jb];
        float am[4] = {av.x, av.y, av.z, av.w};
        float em[4] = {er4.x, er4.y, er4.z, er4.w};
#pragma unroll
        for (int c = 0; c < 4; c++) {
            if (am[c] > 0.f) {
                float e = el + em[c];
                e = (e > 0.f) ? e : 0.2f * e;
                int j = jb * 4 + c;
                const float4* whr = (const float4*)(g_Wh + (size_t)j * 64);
                if (e > m) {
                    float s = __expf(m - e);
                    Z = Z * s + 1.f;
#pragma unroll
                    for (int h = 0; h < 16; h++) {
                        float4 w = __ldg(whr + h);
                        acc[h].x = acc[h].x * s + w.x;
                        acc[h].y = acc[h].y * s + w.y;
                        acc[h].z = acc[h].z * s + w.z;
                        acc[h].w = acc[h].w * s + w.w;
                    }
                    m = e;
                } else {
                    float p = __expf(e - m);
                    Z += p;
#pragma unroll
                    for (int h = 0; h < 16; h++) {
                        float4 w = __ldg(whr + h);
                        acc[h].x += p * w.x;
                        acc[h].y += p * w.y;
                        acc[h].z += p * w.z;
                        acc[h].w += p * w.w;
                    }
                }
            }
        }
    }
    // combine lanes: rescale to warp max, then butterfly-sum Z and acc
    float mw = m;
#pragma unroll
    for (int o = 16; o; o >>= 1) mw = fmaxf(mw, __shfl_xor_sync(FULLMASK, mw, o));
    float s = __expf(m - mw);
    Z *= s;
#pragma unroll
    for (int h = 0; h < 16; h++) {
        acc[h].x *= s; acc[h].y *= s; acc[h].z *= s; acc[h].w *= s;
    }
#pragma unroll
    for (int o = 16; o; o >>= 1) {
        Z += __shfl_xor_sync(FULLMASK, Z, o);
#pragma unroll
        for (int h = 0; h < 16; h++) {
            acc[h].x += __shfl_xor_sync(FULLMASK, acc[h].x, o);
            acc[h].y += __shfl_xor_sync(FULLMASK, acc[h].y, o);
            acc[h].z += __shfl_xor_sync(FULLMASK, acc[h].z, o);
            acc[h].w += __shfl_xor_sync(FULLMASK, acc[h].w, o);
        }
    }
    if (lane == 0) {
        float inv = 1.f / Z;
        float4* outp = (float4*)(g_hgat + (size_t)gw * 64);
#pragma unroll
        for (int h = 0; h < 16; h++) {
            float4 r = acc[h];
            r.x *= inv; r.y *= inv; r.z *= inv; r.w *= inv;
            r.x = (r.x > 0.f) ? r.x : (__expf(r.x) - 1.f);
            r.y = (r.y > 0.f) ? r.y : (__expf(r.y) - 1.f);
            r.z = (r.z > 0.f) ? r.z : (__expf(r.z) - 1.f);
            r.w = (r.w > 0.f) ? r.w : (__expf(r.w) - 1.f);
            outp[h] = r;
        }
    }
}

// ------------------- K3: qkv = h_gat @ Wqkv + b (warp per row; q pre-scaled 1/8) -------------------
__global__ void __launch_bounds__(256) k3_qkv(const float* __restrict__ Wqkv,
                                              const float* __restrict__ bqkv) {
    __shared__ float Wsm[64 * 192];  // 48KB
    int tid = threadIdx.x;
    for (int i = tid; i < 64 * 192; i += 256) Wsm[i] = Wqkv[i];
    __syncthreads();
    int gw = blockIdx.x * 8 + (tid >> 5);
    int lane = tid & 31;
    const float* xr = g_hgat + (size_t)gw * 64;
    float x0 = xr[lane], x1 = xr[lane + 32];
    float acc[6] = {0.f, 0.f, 0.f, 0.f, 0.f, 0.f};
#pragma unroll
    for (int k = 0; k < 64; k++) {
        float xk = __shfl_sync(FULLMASK, (k < 32) ? x0 : x1, k & 31);
#pragma unroll
        for (int u = 0; u < 6; u++) acc[u] += xk * Wsm[k * 192 + lane + 32 * u];
    }
    size_t base = (size_t)gw * 64;
    g_q[base + lane]      = (acc[0] + __ldg(bqkv + lane))       * 0.125f;
    g_q[base + lane + 32] = (acc[1] + __ldg(bqkv + lane + 32))  * 0.125f;
    g_k[base + lane]      =  acc[2] + __ldg(bqkv + 64 + lane);
    g_k[base + lane + 32] =  acc[3] + __ldg(bqkv + 96 + lane);
    g_v[base + lane]      =  acc[4] + __ldg(bqkv + 128 + lane);
    g_v[base + lane + 32] =  acc[5] + __ldg(bqkv + 160 + lane);
}

// ------------------- K4: flash attention, tf32 mma.sync (BM=64, BN=64, d=64) -------------------
#define KPAD 68   // P shares this buffer; pad 68 => conflict-free B/A frag loads
#define VPAD 72   // pad 72 => conflict-free V B-frag loads

__global__ void __launch_bounds__(128) k4_attn() {
    __shared__ float Ksm[64 * KPAD];  // reused as P after S-phase
    __shared__ float Vsm[64 * VPAD];
    int tid = threadIdx.x, lane = tid & 31, warp = tid >> 5;
    int g = lane >> 2, t = lane & 3;
    int view = blockIdx.y;
    int row0 = blockIdx.x * 64;
    size_t vbase = (size_t)view * NN * 64;

    // Q fragments (A, m16k8 x 8 chunks), tf32
    uint32_t qf[8][4];
    {
        const float* Q = g_q + vbase + (size_t)(row0 + warp * 16) * 64;
#pragma unroll
        for (int kc = 0; kc < 8; kc++) {
            qf[kc][0] = f2tf(Q[g * 64 + kc * 8 + t]);
            qf[kc][1] = f2tf(Q[(g + 8) * 64 + kc * 8 + t]);
            qf[kc][2] = f2tf(Q[g * 64 + kc * 8 + t + 4]);
            qf[kc][3] = f2tf(Q[(g + 8) * 64 + kc * 8 + t + 4]);
        }
    }
    float m0 = NEGBIG, m1 = NEGBIG, l0 = 0.f, l1 = 0.f;
    float o[8][4];
#pragma unroll
    for (int db = 0; db < 8; db++) { o[db][0] = o[db][1] = o[db][2] = o[db][3] = 0.f; }

    for (int kt = 0; kt < NN / 64; kt++) {
        __syncthreads();  // prior tile's Vsm / P fully consumed
        const float* Kg = g_k + vbase + (size_t)kt * 64 * 64;
        const float* Vg = g_v + vbase + (size_t)kt * 64 * 64;
        for (int i = tid; i < 64 * 64; i += 128) {
            int r = i >> 6, c = i & 63;
            Ksm[r * KPAD + c] = __uint_as_float(f2tf(Kg[i]));
            Vsm[r * VPAD + c] = __uint_as_float(f2tf(Vg[i]));
        }
        __syncthreads();

        // S = Q K^T  (per-warp m16 x n64)
        float s[8][4];
#pragma unroll
        for (int nb = 0; nb < 8; nb++) { s[nb][0] = s[nb][1] = s[nb][2] = s[nb][3] = 0.f; }
#pragma unroll
        for (int kc = 0; kc < 8; kc++) {
#pragma unroll
            for (int nb = 0; nb < 8; nb++) {
                uint32_t b0 = __float_as_uint(Ksm[(nb * 8 + g) * KPAD + kc * 8 + t]);
                uint32_t b1 = __float_as_uint(Ksm[(nb * 8 + g) * KPAD + kc * 8 + t + 4]);
                mma_tf32(s[nb], qf[kc], b0, b1);
            }
        }
        __syncthreads();  // everyone done reading Ksm before P overwrites it

        // online softmax: rows (g) and (g+8); reduce across the 4 lanes sharing g
        float tm0 = NEGBIG, tm1 = NEGBIG;
#pragma unroll
        for (int nb = 0; nb < 8; nb++) {
            tm0 = fmaxf(tm0, fmaxf(s[nb][0], s[nb][1]));
            tm1 = fmaxf(tm1, fmaxf(s[nb][2], s[nb][3]));
        }
#pragma unroll
        for (int off = 1; off <= 2; off <<= 1) {
            tm0 = fmaxf(tm0, __shfl_xor_sync(FULLMASK, tm0, off));
            tm1 = fmaxf(tm1, __shfl_xor_sync(FULLMASK, tm1, off));
        }
        float nm0 = fmaxf(m0, tm0), nm1 = fmaxf(m1, tm1);
        float c0 = __expf(m0 - nm0), c1 = __expf(m1 - nm1);
        float r0 = 0.f, r1 = 0.f;
#pragma unroll
        for (int nb = 0; nb < 8; nb++) {
            s[nb][0] = __expf(s[nb][0] - nm0);
            s[nb][1] = __expf(s[nb][1] - nm0);
            s[nb][2] = __expf(s[nb][2] - nm1);
            s[nb][3] = __expf(s[nb][3] - nm1);
            r0 += s[nb][0] + s[nb][1];
            r1 += s[nb][2] + s[nb][3];
        }
#pragma unroll
        for (int off = 1; off <= 2; off <<= 1) {
            r0 += __shfl_xor_sync(FULLMASK, r0, off);
            r1 += __shfl_xor_sync(FULLMASK, r1, off);
        }
        l0 = l0 * c0 + r0;
        l1 = l1 * c1 + r1;
#pragma unroll
        for (int db = 0; db < 8; db++) {
            o[db][0] *= c0; o[db][1] *= c0; o[db][2] *= c1; o[db][3] *= c1;
        }
        m0 = nm0; m1 = nm1;

        // store P (tf32) into warp-private rows of the Ksm buffer
        float* Pw = Ksm + warp * 16 * KPAD;
#pragma unroll
        for (int nb = 0; nb < 8; nb++) {
            Pw[g * KPAD + nb * 8 + 2 * t]           = __uint_as_float(f2tf(s[nb][0]));
            Pw[g * KPAD + nb * 8 + 2 * t + 1]       = __uint_as_float(f2tf(s[nb][1]));
            Pw[(g + 8) * KPAD + nb * 8 + 2 * t]     = __uint_as_float(f2tf(s[nb][2]));
            Pw[(g + 8) * KPAD + nb * 8 + 2 * t + 1] = __uint_as_float(f2tf(s[nb][3]));
        }
        __syncwarp();

        // O += P @ V
#pragma unroll
        for (int kc = 0; kc < 8; kc++) {
            uint32_t a0 = __float_as_uint(Pw[g * KPAD + kc * 8 + t]);
            uint32_t a1 = __float_as_uint(Pw[(g + 8) * KPAD + kc * 8 + t]);
            uint32_t a2 = __float_as_uint(Pw[g * KPAD + kc * 8 + t + 4]);
            uint32_t a3 = __float_as_uint(Pw[(g + 8) * KPAD + kc * 8 + t + 4]);
            uint32_t af[4] = {a0, a1, a2, a3};
#pragma unroll
            for (int db = 0; db < 8; db++) {
                uint32_t b0 = __float_as_uint(Vsm[(kc * 8 + t) * VPAD + db * 8 + g]);
                uint32_t b1 = __float_as_uint(Vsm[(kc * 8 + t + 4) * VPAD + db * 8 + g]);
                mma_tf32(o[db], af, b0, b1);
            }
        }
    }
    // epilogue
    float i0 = 1.f / l0, i1 = 1.f / l1;
    float* Og = g_vals + vbase + (size_t)(row0 + warp * 16) * 64;
#pragma unroll
    for (int db = 0; db < 8; db++) {
        Og[g * 64 + db * 8 + 2 * t]           = o[db][0] * i0;
        Og[g * 64 + db * 8 + 2 * t + 1]       = o[db][1] * i0;
        Og[(g + 8) * 64 + db * 8 + 2 * t]     = o[db][2] * i1;
        Og[(g + 8) * 64 + db * 8 + 2 * t + 1] = o[db][3] * i1;
    }
}

// ------------------- K5: o-proj + fusion (warp per node, loops views) -------------------
__global__ void __launch_bounds__(256) k5_fuse(const float* __restrict__ Wo,
                                               const float* __restrict__ bo,
                                               const float* __restrict__ Wf,
                                               const float* __restrict__ bf,
                                               float* __restrict__ out) {
    __shared__ float Wos[64 * 64];
    __shared__ float Wfs[64 * 64];
    int tid = threadIdx.x;
    for (int i = tid; i < 64 * 64; i += 256) { Wos[i] = Wo[i]; Wfs[i] = Wf[i]; }
    __syncthreads();
    int node = blockIdx.x * 8 + (tid >> 5);
    int lane = tid & 31;
    float bo0 = __ldg(bo + lane), bo1 = __ldg(bo + lane + 32);
    float bf0 = __ldg(bf + lane), bf1 = __ldg(bf + lane + 32);
    float fs0 = 0.f, fs1 = 0.f;
    float* vh_out = out + 1024 * 64;
    for (int v = 0; v < VV; v++) {
        const float* vr = g_vals + ((size_t)v * NN + node) * 64;
        float x0 = vr[lane], x1 = vr[lane + 32];
        float o0 = bo0, o1 = bo1;
#pragma unroll
        for (int k = 0; k < 64; k++) {
            float xk = __shfl_sync(FULLMASK, (k < 32) ? x0 : x1, k & 31);
            o0 += xk * Wos[k * 64 + lane];
            o1 += xk * Wos[k * 64 + lane + 32];
        }
        const float* hg = g_hgat + ((size_t)v * NN + node) * 64;
        float hf0 = 0.8f * o0 + 0.2f * hg[lane];
        float hf1 = 0.8f * o1 + 0.2f * hg[lane + 32];
        float w0 = bf0, w1 = bf1;
#pragma unroll
        for (int k = 0; k < 64; k++) {
            float hk = __shfl_sync(FULLMASK, (k < 32) ? hf0 : hf1, k & 31);
            w0 += hk * Wfs[k * 64 + lane];
            w1 += hk * Wfs[k * 64 + lane + 32];
        }
        w0 = 1.f / (1.f + __expf(-w0));
        w1 = 1.f / (1.f + __expf(-w1));
        float hid0 = w0 * hf0, hid1 = w1 * hf1;
        fs0 += hid0; fs1 += hid1;
        float* vh = vh_out + ((size_t)v * NN + node) * 64;
        vh[lane]      = 0.5f * hid0 + 0.5f * hf0;
        vh[lane + 32] = 0.5f * hid1 + 0.5f * hf1;
    }
    if (node >= 2048) {
        float* fo = out + (size_t)(node - 2048) * 64;
        fo[lane] = fs0;
        fo[lane + 32] = fs1;
    }
}

// ------------------- launch -------------------
extern "C" void kernel_launch(void* const* d_in, const int* in_sizes, int n_in,
                              void* d_out, int out_size) {
    const float* adj  = (const float*)d_in[0];
    const float* nf   = (const float*)d_in[1];
    const float* W    = (const float*)d_in[2];
    const float* a    = (const float*)d_in[3];
    const float* Wqkv = (const float*)d_in[4];
    const float* bqkv = (const float*)d_in[5];
    const float* Wo   = (const float*)d_in[6];
    const float* bo   = (const float*)d_in[7];
    const float* Wf   = (const float*)d_in[8];
    const float* bf   = (const float*)d_in[9];
    float* out = (float*)d_out;

    k1_wh<<<NN / 8, 256>>>(nf, W, a);
    k2_gat<<<VV * NN / 8, 256>>>(adj);
    k3_qkv<<<VV * NN / 8, 256>>>(Wqkv, bqkv);
    k4_attn<<<dim3(NN / 64, VV), 128>>>();
    k5_fuse<<<NN / 8, 256>>>(Wo, bo, Wf, bf, out);
}

// round 3
// speedup vs baseline: 1.9837x; 1.9837x over previous
#include <cuda_runtime.h>
#include <cstdint>

#define NN 3072
#define HH 64
#define VV 4
#define SPLITS 4
#define FULLMASK 0xFFFFFFFFu
#define NEGBIG (-1e30f)

// ------------------- scratch (device globals; no allocations) -------------------
__device__ float g_Wh[NN * HH];
__device__ float g_el[NN];
__device__ float g_er[NN];
__device__ float g_hgat[VV * NN * HH];
__device__ float g_q[VV * NN * HH];
__device__ float g_k[VV * NN * HH];
__device__ float g_v[VV * NN * HH];
__device__ float g_vals[VV * NN * HH];
__device__ float g_po[SPLITS * VV * NN * HH];   // split-K partial O (unnormalized)
__device__ float g_pm[SPLITS * VV * NN];        // split-K partial row max
__device__ float g_pl[SPLITS * VV * NN];        // split-K partial row sum

__device__ __forceinline__ uint32_t f2tf(float f) {
    uint32_t u;
    asm("cvt.rna.tf32.f32 %0, %1;" : "=r"(u) : "f"(f));
    return u;
}
__device__ __forceinline__ float tfround(float f) { return __uint_as_float(f2tf(f)); }

__device__ __forceinline__ void mma_tf32(float* d, const uint32_t* a, uint32_t b0, uint32_t b1) {
    asm volatile(
        "mma.sync.aligned.m16n8k8.row.col.f32.tf32.tf32.f32 "
        "{%0,%1,%2,%3}, {%4,%5,%6,%7}, {%8,%9}, {%0,%1,%2,%3};"
        : "+f"(d[0]), "+f"(d[1]), "+f"(d[2]), "+f"(d[3])
        : "r"(a[0]), "r"(a[1]), "r"(a[2]), "r"(a[3]), "r"(b0), "r"(b1));
}

__device__ __forceinline__ void cp16(float* dst, const float* src) {
    uint32_t d = (uint32_t)__cvta_generic_to_shared(dst);
    asm volatile("cp.async.ca.shared.global [%0], [%1], 16;\n" :: "r"(d), "l"(src));
}

// ------------------- K1: Wh = X @ W ; el = Wh@a[:H] ; er = Wh@a[H:] -------------------
__global__ void k1_wh(const float* __restrict__ x, const float* __restrict__ W,
                      const float* __restrict__ a) {
    __shared__ float Wsm[64 * 64];
    __shared__ float a_sm[128];
    int tid = threadIdx.x;
    for (int i = tid; i < 64 * 64; i += 256) Wsm[i] = W[i];
    if (tid < 128) a_sm[tid] = a[tid];
    __syncthreads();
    int warp = tid >> 5, lane = tid & 31;
    int row = blockIdx.x * 8 + warp;
    const float* xr = x + row * 64;
    float x0 = xr[lane], x1 = xr[lane + 32];
    float wh0 = 0.f, wh1 = 0.f;
#pragma unroll
    for (int k = 0; k < 64; k++) {
        float xk = __shfl_sync(FULLMASK, (k < 32) ? x0 : x1, k & 31);
        wh0 += xk * Wsm[k * 64 + lane];
        wh1 += xk * Wsm[k * 64 + lane + 32];
    }
    g_Wh[row * 64 + lane] = wh0;
    g_Wh[row * 64 + lane + 32] = wh1;
    float pl = wh0 * a_sm[lane] + wh1 * a_sm[lane + 32];
    float pr = wh0 * a_sm[64 + lane] + wh1 * a_sm[96 + lane];
#pragma unroll
    for (int o = 16; o; o >>= 1) {
        pl += __shfl_xor_sync(FULLMASK, pl, o);
        pr += __shfl_xor_sync(FULLMASK, pr, o);
    }
    if (lane == 0) { g_el[row] = pl; g_er[row] = pr; }
}

// ------------------- K2: dense tensor-core GAT with fixed row-max -------------------
// p_ij = adj>0 ? exp(lrelu(el_i+er_j) - m_i) : 0, m_i = lrelu(el_i + max(er)) >= true max.
// O_i = (sum_j p_ij Wh_j) / (sum_j p_ij); ELU at the end. All tf32 operands rna-rounded
// (unbiased) — truncation bias was what pushed round-2 rel_err over 1e-3.
#define WHPAD 72

__global__ void __launch_bounds__(256) k2_gat(const float* __restrict__ adj) {
    __shared__ float whs[2][64 * WHPAD];   // 36.9KB
    __shared__ float wred[8];
    int tid = threadIdx.x, warp = tid >> 5, lane = tid & 31;
    int g = lane >> 2, t = lane & 3;
    int grp = warp >> 2, rw = warp & 3;
    int v = blockIdx.y, row0 = blockIdx.x * 64;

    // er_max (block-wide reduction over g_er, L2-hot)
    float mx = NEGBIG;
    for (int i = tid; i < NN; i += 256) mx = fmaxf(mx, __ldg(&g_er[i]));
#pragma unroll
    for (int o = 16; o; o >>= 1) mx = fmaxf(mx, __shfl_xor_sync(FULLMASK, mx, o));
    if (lane == 0) wred[warp] = mx;
    __syncthreads();
    float ermax = wred[0];
#pragma unroll
    for (int i = 1; i < 8; i++) ermax = fmaxf(ermax, wred[i]);

    int r0 = row0 + rw * 16 + g;
    float el0 = __ldg(&g_el[r0]), el1 = __ldg(&g_el[r0 + 8]);
    float m0 = el0 + ermax; m0 = (m0 > 0.f) ? m0 : 0.2f * m0;
    float m1 = el1 + ermax; m1 = (m1 > 0.f) ? m1 : 0.2f * m1;

    float o_[8][4];
#pragma unroll
    for (int db = 0; db < 8; db++) { o_[db][0] = o_[db][1] = o_[db][2] = o_[db][3] = 0.f; }
    float z0 = 0.f, z1 = 0.f;
    const float* arow0 = adj + ((size_t)v * NN + r0) * NN;
    const float* arow1 = arow0 + (size_t)8 * NN;

    for (int jt2 = 0; jt2 < NN / 128; jt2++) {
        __syncthreads();
        const float4* Wg = (const float4*)(g_Wh + (size_t)jt2 * 128 * 64);
        for (int i = tid; i < 2048; i += 256) {       // 2 tiles x 1024 float4
            int b = i >> 10, ii = i & 1023;
            int r = ii >> 4, c = ii & 15;
            float4 w = Wg[b * 1024 + ii];
            w.x = tfround(w.x); w.y = tfround(w.y);
            w.z = tfround(w.z); w.w = tfround(w.w);
            *(float4*)&whs[b][r * WHPAD + c * 4] = w;
        }
        __syncthreads();
        const float* wh = whs[grp];
        int j0 = jt2 * 128 + grp * 64;
#pragma unroll
        for (int kc = 0; kc < 8; kc++) {
            int jc = j0 + kc * 8;
            float a00 = __ldcs(arow0 + jc + t);
            float a10 = __ldcs(arow1 + jc + t);
            float a01 = __ldcs(arow0 + jc + t + 4);
            float a11 = __ldcs(arow1 + jc + t + 4);
            float erA = __ldg(&g_er[jc + t]), erB = __ldg(&g_er[jc + t + 4]);
            float eA0 = el0 + erA; eA0 = (eA0 > 0.f) ? eA0 : 0.2f * eA0;
            float eA1 = el1 + erA; eA1 = (eA1 > 0.f) ? eA1 : 0.2f * eA1;
            float eB0 = el0 + erB; eB0 = (eB0 > 0.f) ? eB0 : 0.2f * eB0;
            float eB1 = el1 + erB; eB1 = (eB1 > 0.f) ? eB1 : 0.2f * eB1;
            // rna-rounded tf32 weights; use the SAME rounded value in z so the
            // softmax numerator/denominator stay consistent.
            float p00 = (a00 > 0.f) ? tfround(__expf(eA0 - m0)) : 0.f;
            float p10 = (a10 > 0.f) ? tfround(__expf(eA1 - m1)) : 0.f;
            float p01 = (a01 > 0.f) ? tfround(__expf(eB0 - m0)) : 0.f;
            float p11 = (a11 > 0.f) ? tfround(__expf(eB1 - m1)) : 0.f;
            z0 += p00 + p01;
            z1 += p10 + p11;
            uint32_t af[4] = {__float_as_uint(p00), __float_as_uint(p10),
                              __float_as_uint(p01), __float_as_uint(p11)};
#pragma unroll
            for (int db = 0; db < 8; db++) {
                uint32_t b0 = __float_as_uint(wh[(kc * 8 + t) * WHPAD + db * 8 + g]);
                uint32_t b1 = __float_as_uint(wh[(kc * 8 + t + 4) * WHPAD + db * 8 + g]);
                mma_tf32(o_[db], af, b0, b1);
            }
        }
    }
    // combine the two j-halves (fixed m => plain sums)
    __syncthreads();
    float* scr = whs[0];
    if (grp == 1) {
        float* p = scr + (rw * 32 + lane) * 34;
#pragma unroll
        for (int db = 0; db < 8; db++) {
            p[db * 4] = o_[db][0]; p[db * 4 + 1] = o_[db][1];
            p[db * 4 + 2] = o_[db][2]; p[db * 4 + 3] = o_[db][3];
        }
        p[32] = z0; p[33] = z1;
    }
    __syncthreads();
    if (grp == 0) {
        const float* p = scr + (rw * 32 + lane) * 34;
#pragma unroll
        for (int db = 0; db < 8; db++) {
            o_[db][0] += p[db * 4]; o_[db][1] += p[db * 4 + 1];
            o_[db][2] += p[db * 4 + 2]; o_[db][3] += p[db * 4 + 3];
        }
        z0 += p[32]; z1 += p[33];
#pragma unroll
        for (int off = 1; off <= 2; off <<= 1) {
            z0 += __shfl_xor_sync(FULLMASK, z0, off);
            z1 += __shfl_xor_sync(FULLMASK, z1, off);
        }
        float i0 = 1.f / z0, i1 = 1.f / z1;
        float* H0 = g_hgat + ((size_t)v * NN + r0) * 64;
        float* H1 = H0 + 8 * 64;
#pragma unroll
        for (int db = 0; db < 8; db++) {
            float r00 = o_[db][0] * i0, r01 = o_[db][1] * i0;
            float r10 = o_[db][2] * i1, r11 = o_[db][3] * i1;
            r00 = (r00 > 0.f) ? r00 : (__expf(r00) - 1.f);
            r01 = (r01 > 0.f) ? r01 : (__expf(r01) - 1.f);
            r10 = (r10 > 0.f) ? r10 : (__expf(r10) - 1.f);
            r11 = (r11 > 0.f) ? r11 : (__expf(r11) - 1.f);
            H0[db * 8 + 2 * t]     = r00;
            H0[db * 8 + 2 * t + 1] = r01;
            H1[db * 8 + 2 * t]     = r10;
            H1[db * 8 + 2 * t + 1] = r11;
        }
    }
}

// ------------------- K3: qkv = h_gat @ Wqkv + b -------------------
// q pre-scaled by 1/8; k,v,q stored ALREADY tf32-rna-rounded so K4's cp.async
// path feeds exact tf32 to the mma (no truncation bias).
__global__ void __launch_bounds__(256) k3_qkv(const float* __restrict__ Wqkv,
                                              const float* __restrict__ bqkv) {
    __shared__ float Wsm[64 * 192];  // 48KB
    int tid = threadIdx.x;
    for (int i = tid; i < 64 * 192; i += 256) Wsm[i] = Wqkv[i];
    __syncthreads();
    int gw = blockIdx.x * 8 + (tid >> 5);
    int lane = tid & 31;
    const float* xr = g_hgat + (size_t)gw * 64;
    float x0 = xr[lane], x1 = xr[lane + 32];
    float acc[6] = {0.f, 0.f, 0.f, 0.f, 0.f, 0.f};
#pragma unroll
    for (int k = 0; k < 64; k++) {
        float xk = __shfl_sync(FULLMASK, (k < 32) ? x0 : x1, k & 31);
#pragma unroll
        for (int u = 0; u < 6; u++) acc[u] += xk * Wsm[k * 192 + lane + 32 * u];
    }
    size_t base = (size_t)gw * 64;
    g_q[base + lane]      = tfround((acc[0] + __ldg(bqkv + lane))      * 0.125f);
    g_q[base + lane + 32] = tfround((acc[1] + __ldg(bqkv + lane + 32)) * 0.125f);
    g_k[base + lane]      = tfround(acc[2] + __ldg(bqkv + 64 + lane));
    g_k[base + lane + 32] = tfround(acc[3] + __ldg(bqkv + 96 + lane));
    g_v[base + lane]      = tfround(acc[4] + __ldg(bqkv + 128 + lane));
    g_v[base + lane + 32] = tfround(acc[5] + __ldg(bqkv + 160 + lane));
}

// ------------------- K4: flash attention, split-K x4, cp.async double buffer -------------------
#define KPAD 68
#define VPAD 72
#define K4_SMEM ((2 * 64 * KPAD + 2 * 64 * VPAD) * 4)

__global__ void __launch_bounds__(128) k4_attn() {
    extern __shared__ float dyn[];
    float* Kbuf[2] = {dyn, dyn + 64 * KPAD};
    float* Vbuf[2] = {dyn + 2 * 64 * KPAD, dyn + 2 * 64 * KPAD + 64 * VPAD};
    int tid = threadIdx.x, lane = tid & 31, warp = tid >> 5;
    int g = lane >> 2, t = lane & 3;
    int view = blockIdx.y;
    int row0 = blockIdx.x * 64;
    int sp = blockIdx.z;
    const int NT = NN / 64 / SPLITS;   // 12
    int kt0 = sp * NT;
    size_t vbase = (size_t)view * NN * 64;

    uint32_t qf[8][4];
    {
        const float* Q = g_q + vbase + (size_t)(row0 + warp * 16) * 64;
#pragma unroll
        for (int kc = 0; kc < 8; kc++) {
            qf[kc][0] = __float_as_uint(Q[g * 64 + kc * 8 + t]);
            qf[kc][1] = __float_as_uint(Q[(g + 8) * 64 + kc * 8 + t]);
            qf[kc][2] = __float_as_uint(Q[g * 64 + kc * 8 + t + 4]);
            qf[kc][3] = __float_as_uint(Q[(g + 8) * 64 + kc * 8 + t + 4]);
        }
    }
    float m0 = NEGBIG, m1 = NEGBIG, l0 = 0.f, l1 = 0.f;
    float o[8][4];
#pragma unroll
    for (int db = 0; db < 8; db++) { o[db][0] = o[db][1] = o[db][2] = o[db][3] = 0.f; }

    auto load_tile = [&](int kt, int buf) {
        const float* Kg = g_k + vbase + (size_t)kt * 4096;
        const float* Vg = g_v + vbase + (size_t)kt * 4096;
        for (int i = tid; i < 1024; i += 128) {
            int r = i >> 4, c = (i & 15) * 4;
            cp16(&Kbuf[buf][r * KPAD + c], Kg + r * 64 + c);
            cp16(&Vbuf[buf][r * VPAD + c], Vg + r * 64 + c);
        }
        asm volatile("cp.async.commit_group;\n");
    };
    load_tile(kt0, 0);

    for (int it = 0; it < NT; it++) {
        int buf = it & 1;
        __syncthreads();   // all compute on buf^1 (incl. its P region) finished
        if (it + 1 < NT) {
            load_tile(kt0 + it + 1, buf ^ 1);
            asm volatile("cp.async.wait_group 1;\n");
        } else {
            asm volatile("cp.async.wait_group 0;\n");
        }
        __syncthreads();   // tile `it` visible to all threads
        float* Ksm = Kbuf[buf];
        float* Vsm = Vbuf[buf];

        // S = Q K^T
        float s[8][4];
#pragma unroll
        for (int nb = 0; nb < 8; nb++) { s[nb][0] = s[nb][1] = s[nb][2] = s[nb][3] = 0.f; }
#pragma unroll
        for (int kc = 0; kc < 8; kc++) {
#pragma unroll
            for (int nb = 0; nb < 8; nb++) {
                uint32_t b0 = __float_as_uint(Ksm[(nb * 8 + g) * KPAD + kc * 8 + t]);
                uint32_t b1 = __float_as_uint(Ksm[(nb * 8 + g) * KPAD + kc * 8 + t + 4]);
                mma_tf32(s[nb], qf[kc], b0, b1);
            }
        }
        __syncthreads();   // Ksm reads done before P overwrites it

        // online softmax
        float tm0 = NEGBIG, tm1 = NEGBIG;
#pragma unroll
        for (int nb = 0; nb < 8; nb++) {
            tm0 = fmaxf(tm0, fmaxf(s[nb][0], s[nb][1]));
            tm1 = fmaxf(tm1, fmaxf(s[nb][2], s[nb][3]));
        }
#pragma unroll
        for (int off = 1; off <= 2; off <<= 1) {
            tm0 = fmaxf(tm0, __shfl_xor_sync(FULLMASK, tm0, off));
            tm1 = fmaxf(tm1, __shfl_xor_sync(FULLMASK, tm1, off));
        }
        float nm0 = fmaxf(m0, tm0), nm1 = fmaxf(m1, tm1);
        float c0 = __expf(m0 - nm0), c1 = __expf(m1 - nm1);
        float r0 = 0.f, r1 = 0.f;
#pragma unroll
        for (int nb = 0; nb < 8; nb++) {
            s[nb][0] = __expf(s[nb][0] - nm0);
            s[nb][1] = __expf(s[nb][1] - nm0);
            s[nb][2] = __expf(s[nb][2] - nm1);
            s[nb][3] = __expf(s[nb][3] - nm1);
            r0 += s[nb][0] + s[nb][1];
            r1 += s[nb][2] + s[nb][3];
        }
#pragma unroll
        for (int off = 1; off <= 2; off <<= 1) {
            r0 += __shfl_xor_sync(FULLMASK, r0, off);
            r1 += __shfl_xor_sync(FULLMASK, r1, off);
        }
        l0 = l0 * c0 + r0;
        l1 = l1 * c1 + r1;
#pragma unroll
        for (int db = 0; db < 8; db++) {
            o[db][0] *= c0; o[db][1] *= c0; o[db][2] *= c1; o[db][3] *= c1;
        }
        m0 = nm0; m1 = nm1;

        // P (tf32 rna) into warp-private rows of Ksm
        float* Pw = Ksm + warp * 16 * KPAD;
#pragma unroll
        for (int nb = 0; nb < 8; nb++) {
            Pw[g * KPAD + nb * 8 + 2 * t]           = tfround(s[nb][0]);
            Pw[g * KPAD + nb * 8 + 2 * t + 1]       = tfround(s[nb][1]);
            Pw[(g + 8) * KPAD + nb * 8 + 2 * t]     = tfround(s[nb][2]);
            Pw[(g + 8) * KPAD + nb * 8 + 2 * t + 1] = tfround(s[nb][3]);
        }
        __syncwarp();

        // O += P @ V
#pragma unroll
        for (int kc = 0; kc < 8; kc++) {
            uint32_t af[4] = {
                __float_as_uint(Pw[g * KPAD + kc * 8 + t]),
                __float_as_uint(Pw[(g + 8) * KPAD + kc * 8 + t]),
                __float_as_uint(Pw[g * KPAD + kc * 8 + t + 4]),
                __float_as_uint(Pw[(g + 8) * KPAD + kc * 8 + t + 4])};
#pragma unroll
            for (int db = 0; db < 8; db++) {
                uint32_t b0 = __float_as_uint(Vsm[(kc * 8 + t) * VPAD + db * 8 + g]);
                uint32_t b1 = __float_as_uint(Vsm[(kc * 8 + t + 4) * VPAD + db * 8 + g]);
                mma_tf32(o[db], af, b0, b1);
            }
        }
    }
    // write unnormalized partials + (m, l)
    float* P0 = g_po + ((size_t)(sp * VV + view) * NN + row0 + warp * 16) * 64;
#pragma unroll
    for (int db = 0; db < 8; db++) {
        P0[g * 64 + db * 8 + 2 * t]           = o[db][0];
        P0[g * 64 + db * 8 + 2 * t + 1]       = o[db][1];
        P0[(g + 8) * 64 + db * 8 + 2 * t]     = o[db][2];
        P0[(g + 8) * 64 + db * 8 + 2 * t + 1] = o[db][3];
    }
    if (t == 0) {
        int ri = (sp * VV + view) * NN + row0 + warp * 16;
        g_pm[ri + g] = m0;     g_pl[ri + g] = l0;
        g_pm[ri + g + 8] = m1; g_pl[ri + g + 8] = l1;
    }
}

// ------------------- K4c: split-K combine -------------------
__global__ void __launch_bounds__(256) k4c_combine() {
    int tid = threadIdx.x, warp = tid >> 5, lane = tid & 31;
    int gw = blockIdx.x * 8 + warp;   // v*NN + node
    float ms[SPLITS];
    float M = NEGBIG;
#pragma unroll
    for (int s = 0; s < SPLITS; s++) {
        ms[s] = __ldg(&g_pm[s * (VV * NN) + gw]);
        M = fmaxf(M, ms[s]);
    }
    float c[SPLITS];
    float den = 0.f;
#pragma unroll
    for (int s = 0; s < SPLITS; s++) {
        c[s] = __expf(ms[s] - M);
        den += __ldg(&g_pl[s * (VV * NN) + gw]) * c[s];
    }
    float inv = 1.f / den;
    float n0 = 0.f, n1 = 0.f;
#pragma unroll
    for (int s = 0; s < SPLITS; s++) {
        const float* p = g_po + ((size_t)s * (VV * NN) + gw) * 64;
        n0 += p[lane] * c[s];
        n1 += p[lane + 32] * c[s];
    }
    g_vals[(size_t)gw * 64 + lane]      = n0 * inv;
    g_vals[(size_t)gw * 64 + lane + 32] = n1 * inv;
}

// ------------------- K5: o-proj + fusion (warp per node, loops views) -------------------
__global__ void __launch_bounds__(256) k5_fuse(const float* __restrict__ Wo,
                                               const float* __restrict__ bo,
                                               const float* __restrict__ Wf,
                                               const float* __restrict__ bf,
                                               float* __restrict__ out) {
    __shared__ float Wos[64 * 64];
    __shared__ float Wfs[64 * 64];
    int tid = threadIdx.x;
    for (int i = tid; i < 64 * 64; i += 256) { Wos[i] = Wo[i]; Wfs[i] = Wf[i]; }
    __syncthreads();
    int node = blockIdx.x * 8 + (tid >> 5);
    int lane = tid & 31;
    float bo0 = __ldg(bo + lane), bo1 = __ldg(bo + lane + 32);
    float bf0 = __ldg(bf + lane), bf1 = __ldg(bf + lane + 32);
    float fs0 = 0.f, fs1 = 0.f;
    float* vh_out = out + 1024 * 64;
    for (int v = 0; v < VV; v++) {
        const float* vr = g_vals + ((size_t)v * NN + node) * 64;
        float x0 = vr[lane], x1 = vr[lane + 32];
        float o0 = bo0, o1 = bo1;
#pragma unroll
        for (int k = 0; k < 64; k++) {
            float xk = __shfl_sync(FULLMASK, (k < 32) ? x0 : x1, k & 31);
            o0 += xk * Wos[k * 64 + lane];
            o1 += xk * Wos[k * 64 + lane + 32];
        }
        const float* hg = g_hgat + ((size_t)v * NN + node) * 64;
        float hf0 = 0.8f * o0 + 0.2f * hg[lane];
        float hf1 = 0.8f * o1 + 0.2f * hg[lane + 32];
        float w0 = bf0, w1 = bf1;
#pragma unroll
        for (int k = 0; k < 64; k++) {
            float hk = __shfl_sync(FULLMASK, (k < 32) ? hf0 : hf1, k & 31);
            w0 += hk * Wfs[k * 64 + lane];
            w1 += hk * Wfs[k * 64 + lane + 32];
        }
        w0 = 1.f / (1.f + __expf(-w0));
        w1 = 1.f / (1.f + __expf(-w1));
        float hid0 = w0 * hf0, hid1 = w1 * hf1;
        fs0 += hid0; fs1 += hid1;
        float* vh = vh_out + ((size_t)v * NN + node) * 64;
        vh[lane]      = 0.5f * hid0 + 0.5f * hf0;
        vh[lane + 32] = 0.5f * hid1 + 0.5f * hf1;
    }
    if (node >= 2048) {
        float* fo = out + (size_t)(node - 2048) * 64;
        fo[lane] = fs0;
        fo[lane + 32] = fs1;
    }
}

// ------------------- launch -------------------
extern "C" void kernel_launch(void* const* d_in, const int* in_sizes, int n_in,
                              void* d_out, int out_size) {
    const float* adj  = (const float*)d_in[0];
    const float* nf   = (const float*)d_in[1];
    const float* W    = (const float*)d_in[2];
    const float* a    = (const float*)d_in[3];
    const float* Wqkv = (const float*)d_in[4];
    const float* bqkv = (const float*)d_in[5];
    const float* Wo   = (const float*)d_in[6];
    const float* bo   = (const float*)d_in[7];
    const float* Wf   = (const float*)d_in[8];
    const float* bf   = (const float*)d_in[9];
    float* out = (float*)d_out;

    cudaFuncSetAttribute(k4_attn, cudaFuncAttributeMaxDynamicSharedMemorySize, K4_SMEM);

    k1_wh<<<NN / 8, 256>>>(nf, W, a);
    k2_gat<<<dim3(NN / 64, VV), 256>>>(adj);
    k3_qkv<<<VV * NN / 8, 256>>>(Wqkv, bqkv);
    k4_attn<<<dim3(NN / 64, VV, SPLITS), 128, K4_SMEM>>>();
    k4c_combine<<<VV * NN / 8, 256>>>();
    k5_fuse<<<NN / 8, 256>>>(Wo, bo, Wf, bf, out);
}

// round 4
// speedup vs baseline: 2.6283x; 1.3250x over previous
#include <cuda_runtime.h>
#include <cstdint>

#define NN 3072
#define HH 64
#define VV 4
#define SPLITS 4
#define JSPLIT 4
#define FULLMASK 0xFFFFFFFFu
#define NEGBIG (-1e30f)

// ------------------- scratch (device globals; no allocations) -------------------
__device__ float g_Wh[NN * HH];
__device__ float g_el[NN];
__device__ float g_er[NN];
__device__ float g_hgat[VV * NN * HH];
__device__ float g_q[VV * NN * HH];   // tf32-rounded, cols pair-permuted
__device__ float g_k[VV * NN * HH];   // tf32-rounded, cols pair-permuted
__device__ float g_v[VV * NN * HH];   // tf32-rounded, natural layout
__device__ float g_vals[VV * NN * HH];
__device__ float g_po[SPLITS * VV * NN * HH];   // partials (k2 j-split, then k4 split-K)
__device__ float g_pm[SPLITS * VV * NN];        // k4 split-K partial row max
__device__ float g_pl[SPLITS * VV * NN];        // z partials (k2), then k4 row sums

__device__ __forceinline__ uint32_t f2tf(float f) {
    uint32_t u;
    asm("cvt.rna.tf32.f32 %0, %1;" : "=r"(u) : "f"(f));
    return u;
}
__device__ __forceinline__ float tfround(float f) { return __uint_as_float(f2tf(f)); }

// logical col c -> physical col (pairs (t, t+4) adjacent within each 8-group)
__device__ __forceinline__ int permcol(int c) {
    return (c & ~7) | (((c & 3) << 1) | ((c >> 2) & 1));
}

__device__ __forceinline__ void mma_tf32(float* d, const uint32_t* a, uint32_t b0, uint32_t b1) {
    asm volatile(
        "mma.sync.aligned.m16n8k8.row.col.f32.tf32.tf32.f32 "
        "{%0,%1,%2,%3}, {%4,%5,%6,%7}, {%8,%9}, {%0,%1,%2,%3};"
        : "+f"(d[0]), "+f"(d[1]), "+f"(d[2]), "+f"(d[3])
        : "r"(a[0]), "r"(a[1]), "r"(a[2]), "r"(a[3]), "r"(b0), "r"(b1));
}

__device__ __forceinline__ void cp16(float* dst, const float* src) {
    uint32_t d = (uint32_t)__cvta_generic_to_shared(dst);
    asm volatile("cp.async.ca.shared.global [%0], [%1], 16;\n" :: "r"(d), "l"(src));
}

// ------------------- K1: Wh = X @ W ; el = Wh@a[:H] ; er = Wh@a[H:] -------------------
__global__ void k1_wh(const float* __restrict__ x, const float* __restrict__ W,
                      const float* __restrict__ a) {
    __shared__ float Wsm[64 * 64];
    __shared__ float a_sm[128];
    int tid = threadIdx.x;
    for (int i = tid; i < 64 * 64; i += 256) Wsm[i] = W[i];
    if (tid < 128) a_sm[tid] = a[tid];
    __syncthreads();
    int warp = tid >> 5, lane = tid & 31;
    int row = blockIdx.x * 8 + warp;
    const float* xr = x + row * 64;
    float x0 = xr[lane], x1 = xr[lane + 32];
    float wh0 = 0.f, wh1 = 0.f;
#pragma unroll
    for (int k = 0; k < 64; k++) {
        float xk = __shfl_sync(FULLMASK, (k < 32) ? x0 : x1, k & 31);
        wh0 += xk * Wsm[k * 64 + lane];
        wh1 += xk * Wsm[k * 64 + lane + 32];
    }
    g_Wh[row * 64 + lane] = wh0;
    g_Wh[row * 64 + lane + 32] = wh1;
    float pl = wh0 * a_sm[lane] + wh1 * a_sm[lane + 32];
    float pr = wh0 * a_sm[64 + lane] + wh1 * a_sm[96 + lane];
#pragma unroll
    for (int o = 16; o; o >>= 1) {
        pl += __shfl_xor_sync(FULLMASK, pl, o);
        pr += __shfl_xor_sync(FULLMASK, pr, o);
    }
    if (lane == 0) { g_el[row] = pl; g_er[row] = pr; }
}

// ------------------- K2: dense tensor-core GAT, fixed row-max, j-split x4 -------------------
#define WHPAD 72

__global__ void __launch_bounds__(256) k2_gat(const float* __restrict__ adj) {
    __shared__ float whs[2][64 * WHPAD];
    __shared__ float wred[8];
    int tid = threadIdx.x, warp = tid >> 5, lane = tid & 31;
    int g = lane >> 2, t = lane & 3;
    int grp = warp >> 2, rw = warp & 3;
    int v = blockIdx.y, row0 = blockIdx.x * 64, sp = blockIdx.z;

    // er_max (block-wide, L2-hot)
    float mx = NEGBIG;
    for (int i = tid; i < NN; i += 256) mx = fmaxf(mx, __ldg(&g_er[i]));
#pragma unroll
    for (int o = 16; o; o >>= 1) mx = fmaxf(mx, __shfl_xor_sync(FULLMASK, mx, o));
    if (lane == 0) wred[warp] = mx;
    __syncthreads();
    float ermax = wred[0];
#pragma unroll
    for (int i = 1; i < 8; i++) ermax = fmaxf(ermax, wred[i]);

    int r0 = row0 + rw * 16 + g;
    float el0 = __ldg(&g_el[r0]), el1 = __ldg(&g_el[r0 + 8]);
    float m0 = el0 + ermax; m0 = (m0 > 0.f) ? m0 : 0.2f * m0;
    float m1 = el1 + ermax; m1 = (m1 > 0.f) ? m1 : 0.2f * m1;

    float o_[8][4];
#pragma unroll
    for (int db = 0; db < 8; db++) { o_[db][0] = o_[db][1] = o_[db][2] = o_[db][3] = 0.f; }
    float z0 = 0.f, z1 = 0.f;
    const float* arow0 = adj + ((size_t)v * NN + r0) * NN;
    const float* arow1 = arow0 + (size_t)8 * NN;

    const int JT_PER = NN / 128 / JSPLIT;   // 6
    for (int jt2 = sp * JT_PER; jt2 < (sp + 1) * JT_PER; jt2++) {
        __syncthreads();
        const float4* Wg = (const float4*)(g_Wh + (size_t)jt2 * 128 * 64);
        for (int i = tid; i < 2048; i += 256) {
            int b = i >> 10, ii = i & 1023;
            int r = ii >> 4, c = ii & 15;
            float4 w = Wg[b * 1024 + ii];
            w.x = tfround(w.x); w.y = tfround(w.y);
            w.z = tfround(w.z); w.w = tfround(w.w);
            *(float4*)&whs[b][r * WHPAD + c * 4] = w;
        }
        __syncthreads();
        const float* wh = whs[grp];
        int j0 = jt2 * 128 + grp * 64;
#pragma unroll
        for (int kc = 0; kc < 8; kc++) {
            int jc = j0 + kc * 8;
            float a00 = __ldcs(arow0 + jc + t);
            float a10 = __ldcs(arow1 + jc + t);
            float a01 = __ldcs(arow0 + jc + t + 4);
            float a11 = __ldcs(arow1 + jc + t + 4);
            float erA = __ldg(&g_er[jc + t]), erB = __ldg(&g_er[jc + t + 4]);
            float eA0 = el0 + erA; eA0 = (eA0 > 0.f) ? eA0 : 0.2f * eA0;
            float eA1 = el1 + erA; eA1 = (eA1 > 0.f) ? eA1 : 0.2f * eA1;
            float eB0 = el0 + erB; eB0 = (eB0 > 0.f) ? eB0 : 0.2f * eB0;
            float eB1 = el1 + erB; eB1 = (eB1 > 0.f) ? eB1 : 0.2f * eB1;
            float p00 = (a00 > 0.f) ? tfround(__expf(eA0 - m0)) : 0.f;
            float p10 = (a10 > 0.f) ? tfround(__expf(eA1 - m1)) : 0.f;
            float p01 = (a01 > 0.f) ? tfround(__expf(eB0 - m0)) : 0.f;
            float p11 = (a11 > 0.f) ? tfround(__expf(eB1 - m1)) : 0.f;
            z0 += p00 + p01;
            z1 += p10 + p11;
            uint32_t af[4] = {__float_as_uint(p00), __float_as_uint(p10),
                              __float_as_uint(p01), __float_as_uint(p11)};
#pragma unroll
            for (int db = 0; db < 8; db++) {
                uint32_t b0 = __float_as_uint(wh[(kc * 8 + t) * WHPAD + db * 8 + g]);
                uint32_t b1 = __float_as_uint(wh[(kc * 8 + t + 4) * WHPAD + db * 8 + g]);
                mma_tf32(o_[db], af, b0, b1);
            }
        }
    }
    // intra-block combine of the two j-halves, then write PARTIAL sums
    __syncthreads();
    float* scr = whs[0];
    if (grp == 1) {
        float* p = scr + (rw * 32 + lane) * 34;
#pragma unroll
        for (int db = 0; db < 8; db++) {
            p[db * 4] = o_[db][0]; p[db * 4 + 1] = o_[db][1];
            p[db * 4 + 2] = o_[db][2]; p[db * 4 + 3] = o_[db][3];
        }
        p[32] = z0; p[33] = z1;
    }
    __syncthreads();
    if (grp == 0) {
        const float* p = scr + (rw * 32 + lane) * 34;
#pragma unroll
        for (int db = 0; db < 8; db++) {
            o_[db][0] += p[db * 4]; o_[db][1] += p[db * 4 + 1];
            o_[db][2] += p[db * 4 + 2]; o_[db][3] += p[db * 4 + 3];
        }
        z0 += p[32]; z1 += p[33];
#pragma unroll
        for (int off = 1; off <= 2; off <<= 1) {
            z0 += __shfl_xor_sync(FULLMASK, z0, off);
            z1 += __shfl_xor_sync(FULLMASK, z1, off);
        }
        float* P0 = g_po + ((size_t)(sp * VV + v) * NN + r0) * 64;
        float* P1 = P0 + 8 * 64;
#pragma unroll
        for (int db = 0; db < 8; db++) {
            P0[db * 8 + 2 * t]     = o_[db][0];
            P0[db * 8 + 2 * t + 1] = o_[db][1];
            P1[db * 8 + 2 * t]     = o_[db][2];
            P1[db * 8 + 2 * t + 1] = o_[db][3];
        }
        if (t == 0) {
            int ri = (sp * VV + v) * NN + r0;
            g_pl[ri] = z0;
            g_pl[ri + 8] = z1;
        }
    }
}

// ------------------- K2c: combine j-split partials, normalize, ELU -------------------
__global__ void __launch_bounds__(256) k2c_combine() {
    int tid = threadIdx.x, warp = tid >> 5, lane = tid & 31;
    int gw = blockIdx.x * 8 + warp;   // v*NN + node
    float n0 = 0.f, n1 = 0.f, z = 0.f;
#pragma unroll
    for (int s = 0; s < JSPLIT; s++) {
        const float* p = g_po + ((size_t)s * (VV * NN) + gw) * 64;
        n0 += p[lane];
        n1 += p[lane + 32];
        z += __ldg(&g_pl[s * (VV * NN) + gw]);
    }
    float inv = 1.f / z;
    float r0 = n0 * inv, r1 = n1 * inv;
    r0 = (r0 > 0.f) ? r0 : (__expf(r0) - 1.f);
    r1 = (r1 > 0.f) ? r1 : (__expf(r1) - 1.f);
    g_hgat[(size_t)gw * 64 + lane]      = r0;
    g_hgat[(size_t)gw * 64 + lane + 32] = r1;
}

// ------------------- K3: qkv = h_gat @ Wqkv + b -------------------
// q,k stored tf32-rounded AND pair-permuted (so K4 gets float2 fragments); v rounded only.
__global__ void __launch_bounds__(256) k3_qkv(const float* __restrict__ Wqkv,
                                              const float* __restrict__ bqkv) {
    __shared__ float Wsm[64 * 192];
    int tid = threadIdx.x;
    for (int i = tid; i < 64 * 192; i += 256) Wsm[i] = Wqkv[i];
    __syncthreads();
    int gw = blockIdx.x * 8 + (tid >> 5);
    int lane = tid & 31;
    const float* xr = g_hgat + (size_t)gw * 64;
    float x0 = xr[lane], x1 = xr[lane + 32];
    float acc[6] = {0.f, 0.f, 0.f, 0.f, 0.f, 0.f};
#pragma unroll
    for (int k = 0; k < 64; k++) {
        float xk = __shfl_sync(FULLMASK, (k < 32) ? x0 : x1, k & 31);
#pragma unroll
        for (int u = 0; u < 6; u++) acc[u] += xk * Wsm[k * 192 + lane + 32 * u];
    }
    size_t base = (size_t)gw * 64;
    int pc0 = permcol(lane), pc1 = permcol(lane + 32);
    g_q[base + pc0] = tfround((acc[0] + __ldg(bqkv + lane))      * 0.125f);
    g_q[base + pc1] = tfround((acc[1] + __ldg(bqkv + lane + 32)) * 0.125f);
    g_k[base + pc0] = tfround(acc[2] + __ldg(bqkv + 64 + lane));
    g_k[base + pc1] = tfround(acc[3] + __ldg(bqkv + 96 + lane));
    g_v[base + lane]      = tfround(acc[4] + __ldg(bqkv + 128 + lane));
    g_v[base + lane + 32] = tfround(acc[5] + __ldg(bqkv + 160 + lane));
}

// ------------------- K4: flash attention, split-K x4, cp.async, packed LDS.64 -------------------
#define KPAD 72   // 72 mod 32 == 8 -> 8g+2t banks, conflict-free float2 loads
#define VPAD 72
#define K4_SMEM ((2 * 64 * KPAD + 2 * 64 * VPAD) * 4)

__global__ void __launch_bounds__(128, 3) k4_attn() {
    extern __shared__ float dyn[];
    float* Kbuf[2] = {dyn, dyn + 64 * KPAD};
    float* Vbuf[2] = {dyn + 2 * 64 * KPAD, dyn + 2 * 64 * KPAD + 64 * VPAD};
    int tid = threadIdx.x, lane = tid & 31, warp = tid >> 5;
    int g = lane >> 2, t = lane & 3;
    int view = blockIdx.y;
    int row0 = blockIdx.x * 64;
    int sp = blockIdx.z;
    const int NT = NN / 64 / SPLITS;   // 12
    int kt0 = sp * NT;
    size_t vbase = (size_t)view * NN * 64;

    // Q fragments via float2 (g_q is pair-permuted): (x,y) = (col kc*8+t, col kc*8+t+4)
    uint32_t qf[8][4];
    {
        const float* Q = g_q + vbase + (size_t)(row0 + warp * 16) * 64;
        const float2* Qa = (const float2*)(Q + g * 64);
        const float2* Qb = (const float2*)(Q + (g + 8) * 64);
#pragma unroll
        for (int kc = 0; kc < 8; kc++) {
            float2 qa = Qa[kc * 4 + t];
            float2 qb = Qb[kc * 4 + t];
            qf[kc][0] = __float_as_uint(qa.x);
            qf[kc][1] = __float_as_uint(qb.x);
            qf[kc][2] = __float_as_uint(qa.y);
            qf[kc][3] = __float_as_uint(qb.y);
        }
    }
    float m0 = NEGBIG, m1 = NEGBIG, l0 = 0.f, l1 = 0.f;
    float o[8][4];
#pragma unroll
    for (int db = 0; db < 8; db++) { o[db][0] = o[db][1] = o[db][2] = o[db][3] = 0.f; }

    auto load_tile = [&](int kt, int buf) {
        const float* Kg = g_k + vbase + (size_t)kt * 4096;
        const float* Vg = g_v + vbase + (size_t)kt * 4096;
        for (int i = tid; i < 1024; i += 128) {
            int r = i >> 4, c = (i & 15) * 4;
            cp16(&Kbuf[buf][r * KPAD + c], Kg + r * 64 + c);
            cp16(&Vbuf[buf][r * VPAD + c], Vg + r * 64 + c);
        }
        asm volatile("cp.async.commit_group;\n");
    };
    load_tile(kt0, 0);

    for (int it = 0; it < NT; it++) {
        int buf = it & 1;
        __syncthreads();
        if (it + 1 < NT) {
            load_tile(kt0 + it + 1, buf ^ 1);
            asm volatile("cp.async.wait_group 1;\n");
        } else {
            asm volatile("cp.async.wait_group 0;\n");
        }
        __syncthreads();
        float* Ksm = Kbuf[buf];
        float* Vsm = Vbuf[buf];

        // S = Q K^T (K cols pair-permuted -> one float2 per mma B fragment)
        float s[8][4];
#pragma unroll
        for (int nb = 0; nb < 8; nb++) { s[nb][0] = s[nb][1] = s[nb][2] = s[nb][3] = 0.f; }
#pragma unroll
        for (int kc = 0; kc < 8; kc++) {
#pragma unroll
            for (int nb = 0; nb < 8; nb++) {
                float2 kv = *(const float2*)&Ksm[(nb * 8 + g) * KPAD + kc * 8 + 2 * t];
                mma_tf32(s[nb], qf[kc], __float_as_uint(kv.x), __float_as_uint(kv.y));
            }
        }
        __syncthreads();

        // online softmax
        float tm0 = NEGBIG, tm1 = NEGBIG;
#pragma unroll
        for (int nb = 0; nb < 8; nb++) {
            tm0 = fmaxf(tm0, fmaxf(s[nb][0], s[nb][1]));
            tm1 = fmaxf(tm1, fmaxf(s[nb][2], s[nb][3]));
        }
#pragma unroll
        for (int off = 1; off <= 2; off <<= 1) {
            tm0 = fmaxf(tm0, __shfl_xor_sync(FULLMASK, tm0, off));
            tm1 = fmaxf(tm1, __shfl_xor_sync(FULLMASK, tm1, off));
        }
        float nm0 = fmaxf(m0, tm0), nm1 = fmaxf(m1, tm1);
        float c0 = __expf(m0 - nm0), c1 = __expf(m1 - nm1);
        float r0 = 0.f, r1 = 0.f;
#pragma unroll
        for (int nb = 0; nb < 8; nb++) {
            s[nb][0] = __expf(s[nb][0] - nm0);
            s[nb][1] = __expf(s[nb][1] - nm0);
            s[nb][2] = __expf(s[nb][2] - nm1);
            s[nb][3] = __expf(s[nb][3] - nm1);
            r0 += s[nb][0] + s[nb][1];
            r1 += s[nb][2] + s[nb][3];
        }
#pragma unroll
        for (int off = 1; off <= 2; off <<= 1) {
            r0 += __shfl_xor_sync(FULLMASK, r0, off);
            r1 += __shfl_xor_sync(FULLMASK, r1, off);
        }
        l0 = l0 * c0 + r0;
        l1 = l1 * c1 + r1;
#pragma unroll
        for (int db = 0; db < 8; db++) {
            o[db][0] *= c0; o[db][1] *= c0; o[db][2] *= c1; o[db][3] *= c1;
        }
        m0 = nm0; m1 = nm1;

        // P (tf32 rna) stored pair-permuted into warp-private Ksm rows.
        // logical col nb*8+2t -> phys {0,4,1,5}[t]; col nb*8+2t+1 -> phys {2,6,3,7}[t]
        float* Pw = Ksm + warp * 16 * KPAD;
        int ps0 = ((2 * t) & 3) * 2 + (t >> 1);        // 0,4,1,5
        int ps1 = ((2 * t + 1) & 3) * 2 + (t >> 1);    // 2,6,3,7
#pragma unroll
        for (int nb = 0; nb < 8; nb++) {
            Pw[g * KPAD + nb * 8 + ps0]       = tfround(s[nb][0]);
            Pw[g * KPAD + nb * 8 + ps1]       = tfround(s[nb][1]);
            Pw[(g + 8) * KPAD + nb * 8 + ps0] = tfround(s[nb][2]);
            Pw[(g + 8) * KPAD + nb * 8 + ps1] = tfround(s[nb][3]);
        }
        __syncwarp();

        // O += P @ V (P A-fragments via float2)
#pragma unroll
        for (int kc = 0; kc < 8; kc++) {
            float2 pa = *(const float2*)&Pw[g * KPAD + kc * 8 + 2 * t];
            float2 pb = *(const float2*)&Pw[(g + 8) * KPAD + kc * 8 + 2 * t];
            uint32_t af[4] = {__float_as_uint(pa.x), __float_as_uint(pb.x),
                              __float_as_uint(pa.y), __float_as_uint(pb.y)};
#pragma unroll
            for (int db = 0; db < 8; db++) {
                uint32_t b0 = __float_as_uint(Vsm[(kc * 8 + t) * VPAD + db * 8 + g]);
                uint32_t b1 = __float_as_uint(Vsm[(kc * 8 + t + 4) * VPAD + db * 8 + g]);
                mma_tf32(o[db], af, b0, b1);
            }
        }
    }
    // write unnormalized partials + (m, l)
    float* P0 = g_po + ((size_t)(sp * VV + view) * NN + row0 + warp * 16) * 64;
#pragma unroll
    for (int db = 0; db < 8; db++) {
        P0[g * 64 + db * 8 + 2 * t]           = o[db][0];
        P0[g * 64 + db * 8 + 2 * t + 1]       = o[db][1];
        P0[(g + 8) * 64 + db * 8 + 2 * t]     = o[db][2];
        P0[(g + 8) * 64 + db * 8 + 2 * t + 1] = o[db][3];
    }
    if (t == 0) {
        int ri = (sp * VV + view) * NN + row0 + warp * 16;
        g_pm[ri + g] = m0;     g_pl[ri + g] = l0;
        g_pm[ri + g + 8] = m1; g_pl[ri + g + 8] = l1;
    }
}

// ------------------- K4c: split-K combine -------------------
__global__ void __launch_bounds__(256) k4c_combine() {
    int tid = threadIdx.x, warp = tid >> 5, lane = tid & 31;
    int gw = blockIdx.x * 8 + warp;
    float ms[SPLITS];
    float M = NEGBIG;
#pragma unroll
    for (int s = 0; s < SPLITS; s++) {
        ms[s] = __ldg(&g_pm[s * (VV * NN) + gw]);
        M = fmaxf(M, ms[s]);
    }
    float c[SPLITS];
    float den = 0.f;
#pragma unroll
    for (int s = 0; s < SPLITS; s++) {
        c[s] = __expf(ms[s] - M);
        den += __ldg(&g_pl[s * (VV * NN) + gw]) * c[s];
    }
    float inv = 1.f / den;
    float n0 = 0.f, n1 = 0.f;
#pragma unroll
    for (int s = 0; s < SPLITS; s++) {
        const float* p = g_po + ((size_t)s * (VV * NN) + gw) * 64;
        n0 += p[lane] * c[s];
        n1 += p[lane + 32] * c[s];
    }
    g_vals[(size_t)gw * 64 + lane]      = n0 * inv;
    g_vals[(size_t)gw * 64 + lane + 32] = n1 * inv;
}

// ------------------- K5: o-proj + fusion -------------------
__global__ void __launch_bounds__(256) k5_fuse(const float* __restrict__ Wo,
                                               const float* __restrict__ bo,
                                               const float* __restrict__ Wf,
                                               const float* __restrict__ bf,
                                               float* __restrict__ out) {
    __shared__ float Wos[64 * 64];
    __shared__ float Wfs[64 * 64];
    int tid = threadIdx.x;
    for (int i = tid; i < 64 * 64; i += 256) { Wos[i] = Wo[i]; Wfs[i] = Wf[i]; }
    __syncthreads();
    int node = blockIdx.x * 8 + (tid >> 5);
    int lane = tid & 31;
    float bo0 = __ldg(bo + lane), bo1 = __ldg(bo + lane + 32);
    float bf0 = __ldg(bf + lane), bf1 = __ldg(bf + lane + 32);
    float fs0 = 0.f, fs1 = 0.f;
    float* vh_out = out + 1024 * 64;
    for (int v = 0; v < VV; v++) {
        const float* vr = g_vals + ((size_t)v * NN + node) * 64;
        float x0 = vr[lane], x1 = vr[lane + 32];
        float o0 = bo0, o1 = bo1;
#pragma unroll
        for (int k = 0; k < 64; k++) {
            float xk = __shfl_sync(FULLMASK, (k < 32) ? x0 : x1, k & 31);
            o0 += xk * Wos[k * 64 + lane];
            o1 += xk * Wos[k * 64 + lane + 32];
        }
        const float* hg = g_hgat + ((size_t)v * NN + node) * 64;
        float hf0 = 0.8f * o0 + 0.2f * hg[lane];
        float hf1 = 0.8f * o1 + 0.2f * hg[lane + 32];
        float w0 = bf0, w1 = bf1;
#pragma unroll
        for (int k = 0; k < 64; k++) {
            float hk = __shfl_sync(FULLMASK, (k < 32) ? hf0 : hf1, k & 31);
            w0 += hk * Wfs[k * 64 + lane];
            w1 += hk * Wfs[k * 64 + lane + 32];
        }
        w0 = 1.f / (1.f + __expf(-w0));
        w1 = 1.f / (1.f + __expf(-w1));
        float hid0 = w0 * hf0, hid1 = w1 * hf1;
        fs0 += hid0; fs1 += hid1;
        float* vh = vh_out + ((size_t)v * NN + node) * 64;
        vh[lane]      = 0.5f * hid0 + 0.5f * hf0;
        vh[lane + 32] = 0.5f * hid1 + 0.5f * hf1;
    }
    if (node >= 2048) {
        float* fo = out + (size_t)(node - 2048) * 64;
        fo[lane] = fs0;
        fo[lane + 32] = fs1;
    }
}

// ------------------- launch -------------------
extern "C" void kernel_launch(void* const* d_in, const int* in_sizes, int n_in,
                              void* d_out, int out_size) {
    const float* adj  = (const float*)d_in[0];
    const float* nf   = (const float*)d_in[1];
    const float* W    = (const float*)d_in[2];
    const float* a    = (const float*)d_in[3];
    const float* Wqkv = (const float*)d_in[4];
    const float* bqkv = (const float*)d_in[5];
    const float* Wo   = (const float*)d_in[6];
    const float* bo   = (const float*)d_in[7];
    const float* Wf   = (const float*)d_in[8];
    const float* bf   = (const float*)d_in[9];
    float* out = (float*)d_out;

    cudaFuncSetAttribute(k4_attn, cudaFuncAttributeMaxDynamicSharedMemorySize, K4_SMEM);

    k1_wh<<<NN / 8, 256>>>(nf, W, a);
    k2_gat<<<dim3(NN / 64, VV, JSPLIT), 256>>>(adj);
    k2c_combine<<<VV * NN / 8, 256>>>();
    k3_qkv<<<VV * NN / 8, 256>>>(Wqkv, bqkv);
    k4_attn<<<dim3(NN / 64, VV, SPLITS), 128, K4_SMEM>>>();
    k4c_combine<<<VV * NN / 8, 256>>>();
    k5_fuse<<<NN / 8, 256>>>(Wo, bo, Wf, bf, out);
}

// round 5
// speedup vs baseline: 2.7185x; 1.0343x over previous
#include <cuda_runtime.h>
#include <cstdint>

#define NN 3072
#define HH 64
#define VV 4
#define SPLITS 8
#define JSPLIT 8
#define FULLMASK 0xFFFFFFFFu
#define NEGBIG (-1e30f)

// ------------------- scratch (device globals; no allocations) -------------------
__device__ float g_Wh[NN * HH];
__device__ float g_el[NN];
__device__ float g_er[NN];
__device__ float g_hgat[VV * NN * HH];
__device__ float g_q[VV * NN * HH];   // tf32-rounded, cols pair-permuted
__device__ float g_k[VV * NN * HH];   // tf32-rounded, cols pair-permuted
__device__ float g_v[VV * NN * HH];   // tf32-rounded, natural layout
__device__ float g_vals[VV * NN * HH];
__device__ float g_po[SPLITS * VV * NN * HH];   // partials (k2 j-split, then k4 split-K)
__device__ float g_pm[SPLITS * VV * NN];        // k4 split-K partial row max
__device__ float g_pl[SPLITS * VV * NN];        // z partials (k2), then k4 row sums

__device__ __forceinline__ uint32_t f2tf(float f) {
    uint32_t u;
    asm("cvt.rna.tf32.f32 %0, %1;" : "=r"(u) : "f"(f));
    return u;
}
__device__ __forceinline__ float tfround(float f) { return __uint_as_float(f2tf(f)); }

// logical col c -> physical col (pairs (t, t+4) adjacent within each 8-group)
__device__ __forceinline__ int permcol(int c) {
    return (c & ~7) | (((c & 3) << 1) | ((c >> 2) & 1));
}

__device__ __forceinline__ void mma_tf32(float* d, const uint32_t* a, uint32_t b0, uint32_t b1) {
    asm volatile(
        "mma.sync.aligned.m16n8k8.row.col.f32.tf32.tf32.f32 "
        "{%0,%1,%2,%3}, {%4,%5,%6,%7}, {%8,%9}, {%0,%1,%2,%3};"
        : "+f"(d[0]), "+f"(d[1]), "+f"(d[2]), "+f"(d[3])
        : "r"(a[0]), "r"(a[1]), "r"(a[2]), "r"(a[3]), "r"(b0), "r"(b1));
}

__device__ __forceinline__ void cp16(float* dst, const float* src) {
    uint32_t d = (uint32_t)__cvta_generic_to_shared(dst);
    asm volatile("cp.async.ca.shared.global [%0], [%1], 16;\n" :: "r"(d), "l"(src));
}

// ------------------- K1: Wh = X @ W ; el = Wh@a[:H] ; er = Wh@a[H:] -------------------
__global__ void k1_wh(const float* __restrict__ x, const float* __restrict__ W,
                      const float* __restrict__ a) {
    __shared__ float Wsm[64 * 64];
    __shared__ float a_sm[128];
    int tid = threadIdx.x;
    for (int i = tid; i < 64 * 64; i += 256) Wsm[i] = W[i];
    if (tid < 128) a_sm[tid] = a[tid];
    __syncthreads();
    int warp = tid >> 5, lane = tid & 31;
    int row = blockIdx.x * 8 + warp;
    const float* xr = x + row * 64;
    float x0 = xr[lane], x1 = xr[lane + 32];
    float wh0 = 0.f, wh1 = 0.f;
#pragma unroll
    for (int k = 0; k < 64; k++) {
        float xk = __shfl_sync(FULLMASK, (k < 32) ? x0 : x1, k & 31);
        wh0 += xk * Wsm[k * 64 + lane];
        wh1 += xk * Wsm[k * 64 + lane + 32];
    }
    g_Wh[row * 64 + lane] = wh0;
    g_Wh[row * 64 + lane + 32] = wh1;
    float pl = wh0 * a_sm[lane] + wh1 * a_sm[lane + 32];
    float pr = wh0 * a_sm[64 + lane] + wh1 * a_sm[96 + lane];
#pragma unroll
    for (int o = 16; o; o >>= 1) {
        pl += __shfl_xor_sync(FULLMASK, pl, o);
        pr += __shfl_xor_sync(FULLMASK, pr, o);
    }
    if (lane == 0) { g_el[row] = pl; g_er[row] = pr; }
}

// ------------------- K2: dense tensor-core GAT, fixed row-max, j-split -------------------
#define WHPAD 72

__global__ void __launch_bounds__(256) k2_gat(const float* __restrict__ adj) {
    __shared__ float whs[2][64 * WHPAD];
    __shared__ float wred[8];
    int tid = threadIdx.x, warp = tid >> 5, lane = tid & 31;
    int g = lane >> 2, t = lane & 3;
    int grp = warp >> 2, rw = warp & 3;
    int v = blockIdx.y, row0 = blockIdx.x * 64, sp = blockIdx.z;

    // er_max (block-wide, L2-hot)
    float mx = NEGBIG;
    for (int i = tid; i < NN; i += 256) mx = fmaxf(mx, __ldg(&g_er[i]));
#pragma unroll
    for (int o = 16; o; o >>= 1) mx = fmaxf(mx, __shfl_xor_sync(FULLMASK, mx, o));
    if (lane == 0) wred[warp] = mx;
    __syncthreads();
    float ermax = wred[0];
#pragma unroll
    for (int i = 1; i < 8; i++) ermax = fmaxf(ermax, wred[i]);

    int r0 = row0 + rw * 16 + g;
    float el0 = __ldg(&g_el[r0]), el1 = __ldg(&g_el[r0 + 8]);
    float m0 = el0 + ermax; m0 = (m0 > 0.f) ? m0 : 0.2f * m0;
    float m1 = el1 + ermax; m1 = (m1 > 0.f) ? m1 : 0.2f * m1;

    float o_[8][4];
#pragma unroll
    for (int db = 0; db < 8; db++) { o_[db][0] = o_[db][1] = o_[db][2] = o_[db][3] = 0.f; }
    float z0 = 0.f, z1 = 0.f;
    const float* arow0 = adj + ((size_t)v * NN + r0) * NN;
    const float* arow1 = arow0 + (size_t)8 * NN;

    const int JT_PER = NN / 128 / JSPLIT;   // 3
    for (int jt2 = sp * JT_PER; jt2 < (sp + 1) * JT_PER; jt2++) {
        __syncthreads();
        const float4* Wg = (const float4*)(g_Wh + (size_t)jt2 * 128 * 64);
        for (int i = tid; i < 2048; i += 256) {
            int b = i >> 10, ii = i & 1023;
            int r = ii >> 4, c = ii & 15;
            float4 w = Wg[b * 1024 + ii];
            w.x = tfround(w.x); w.y = tfround(w.y);
            w.z = tfround(w.z); w.w = tfround(w.w);
            *(float4*)&whs[b][r * WHPAD + c * 4] = w;
        }
        __syncthreads();
        const float* wh = whs[grp];
        int j0 = jt2 * 128 + grp * 64;
#pragma unroll
        for (int kc = 0; kc < 8; kc++) {
            int jc = j0 + kc * 8;
            float a00 = __ldcs(arow0 + jc + t);
            float a10 = __ldcs(arow1 + jc + t);
            float a01 = __ldcs(arow0 + jc + t + 4);
            float a11 = __ldcs(arow1 + jc + t + 4);
            float erA = __ldg(&g_er[jc + t]), erB = __ldg(&g_er[jc + t + 4]);
            float eA0 = el0 + erA; eA0 = (eA0 > 0.f) ? eA0 : 0.2f * eA0;
            float eA1 = el1 + erA; eA1 = (eA1 > 0.f) ? eA1 : 0.2f * eA1;
            float eB0 = el0 + erB; eB0 = (eB0 > 0.f) ? eB0 : 0.2f * eB0;
            float eB1 = el1 + erB; eB1 = (eB1 > 0.f) ? eB1 : 0.2f * eB1;
            float p00 = (a00 > 0.f) ? tfround(__expf(eA0 - m0)) : 0.f;
            float p10 = (a10 > 0.f) ? tfround(__expf(eA1 - m1)) : 0.f;
            float p01 = (a01 > 0.f) ? tfround(__expf(eB0 - m0)) : 0.f;
            float p11 = (a11 > 0.f) ? tfround(__expf(eB1 - m1)) : 0.f;
            z0 += p00 + p01;
            z1 += p10 + p11;
            uint32_t af[4] = {__float_as_uint(p00), __float_as_uint(p10),
                              __float_as_uint(p01), __float_as_uint(p11)};
#pragma unroll
            for (int db = 0; db < 8; db++) {
                uint32_t b0 = __float_as_uint(wh[(kc * 8 + t) * WHPAD + db * 8 + g]);
                uint32_t b1 = __float_as_uint(wh[(kc * 8 + t + 4) * WHPAD + db * 8 + g]);
                mma_tf32(o_[db], af, b0, b1);
            }
        }
    }
    // intra-block combine of the two j-halves, then write PARTIAL sums
    __syncthreads();
    float* scr = whs[0];
    if (grp == 1) {
        float* p = scr + (rw * 32 + lane) * 34;
#pragma unroll
        for (int db = 0; db < 8; db++) {
            p[db * 4] = o_[db][0]; p[db * 4 + 1] = o_[db][1];
            p[db * 4 + 2] = o_[db][2]; p[db * 4 + 3] = o_[db][3];
        }
        p[32] = z0; p[33] = z1;
    }
    __syncthreads();
    if (grp == 0) {
        const float* p = scr + (rw * 32 + lane) * 34;
#pragma unroll
        for (int db = 0; db < 8; db++) {
            o_[db][0] += p[db * 4]; o_[db][1] += p[db * 4 + 1];
            o_[db][2] += p[db * 4 + 2]; o_[db][3] += p[db * 4 + 3];
        }
        z0 += p[32]; z1 += p[33];
#pragma unroll
        for (int off = 1; off <= 2; off <<= 1) {
            z0 += __shfl_xor_sync(FULLMASK, z0, off);
            z1 += __shfl_xor_sync(FULLMASK, z1, off);
        }
        float* P0 = g_po + ((size_t)(sp * VV + v) * NN + r0) * 64;
        float* P1 = P0 + 8 * 64;
#pragma unroll
        for (int db = 0; db < 8; db++) {
            P0[db * 8 + 2 * t]     = o_[db][0];
            P0[db * 8 + 2 * t + 1] = o_[db][1];
            P1[db * 8 + 2 * t]     = o_[db][2];
            P1[db * 8 + 2 * t + 1] = o_[db][3];
        }
        if (t == 0) {
            int ri = (sp * VV + v) * NN + r0;
            g_pl[ri] = z0;
            g_pl[ri + 8] = z1;
        }
    }
}

// ------------------- K2c: combine j-split partials, normalize, ELU -------------------
__global__ void __launch_bounds__(256) k2c_combine() {
    int tid = threadIdx.x, warp = tid >> 5, lane = tid & 31;
    int gw = blockIdx.x * 8 + warp;   // v*NN + node
    float n0 = 0.f, n1 = 0.f, z = 0.f;
#pragma unroll
    for (int s = 0; s < JSPLIT; s++) {
        const float* p = g_po + ((size_t)s * (VV * NN) + gw) * 64;
        n0 += p[lane];
        n1 += p[lane + 32];
        z += __ldg(&g_pl[s * (VV * NN) + gw]);
    }
    float inv = 1.f / z;
    float r0 = n0 * inv, r1 = n1 * inv;
    r0 = (r0 > 0.f) ? r0 : (__expf(r0) - 1.f);
    r1 = (r1 > 0.f) ? r1 : (__expf(r1) - 1.f);
    g_hgat[(size_t)gw * 64 + lane]      = r0;
    g_hgat[(size_t)gw * 64 + lane + 32] = r1;
}

// ------------------- K3: qkv = h_gat @ Wqkv + b, tensor-core -------------------
// B staged transposed [n=192][k-permuted, pad 72]; A frags rna-tf32 from g_hgat.
// Outputs: q,k tf32-rounded + pair-permuted (q pre-scaled 1/8); v tf32-rounded.
#define BPAD 72
#define K3_SMEM (192 * BPAD * 4)

__global__ void __launch_bounds__(128) k3_qkv(const float* __restrict__ Wqkv,
                                              const float* __restrict__ bqkv) {
    extern __shared__ float Bsm[];   // [192][BPAD], Bsm[n][perm(k)]
    int tid = threadIdx.x, warp = tid >> 5, lane = tid & 31;
    int g = lane >> 2, t = lane & 3;
    for (int i = tid; i < 64 * 192; i += 128) {
        int k = i / 192, n = i % 192;
        Bsm[n * BPAD + permcol(k)] = tfround(Wqkv[i]);
    }
    int row0 = blockIdx.x * 64 + warp * 16;
    // A fragments (16 rows x 64 k)
    uint32_t af[8][4];
    {
        const float* A = g_hgat + (size_t)row0 * 64;
#pragma unroll
        for (int kc = 0; kc < 8; kc++) {
            af[kc][0] = f2tf(A[g * 64 + kc * 8 + t]);
            af[kc][1] = f2tf(A[(g + 8) * 64 + kc * 8 + t]);
            af[kc][2] = f2tf(A[g * 64 + kc * 8 + t + 4]);
            af[kc][3] = f2tf(A[(g + 8) * 64 + kc * 8 + t + 4]);
        }
    }
    float s[24][4];
#pragma unroll
    for (int nb = 0; nb < 24; nb++) { s[nb][0] = s[nb][1] = s[nb][2] = s[nb][3] = 0.f; }
    __syncthreads();
#pragma unroll
    for (int kc = 0; kc < 8; kc++) {
#pragma unroll
        for (int nb = 0; nb < 24; nb++) {
            float2 b = *(const float2*)&Bsm[(nb * 8 + g) * BPAD + kc * 8 + 2 * t];
            mma_tf32(s[nb], af[kc], __float_as_uint(b.x), __float_as_uint(b.y));
        }
    }
    // epilogue: bias, q-scale, tfround, permuted stores
    size_t b0 = (size_t)row0 * 64;
    size_t b1 = (size_t)(row0 + 8) * 64;
#pragma unroll
    for (int nb = 0; nb < 24; nb++) {
        int c0 = nb * 8 + 2 * t, c1 = c0 + 1;
        float bi0 = __ldg(bqkv + c0), bi1 = __ldg(bqkv + c1);
        float v00 = s[nb][0] + bi0, v01 = s[nb][1] + bi1;
        float v10 = s[nb][2] + bi0, v11 = s[nb][3] + bi1;
        if (c0 < 64) {
            int p0 = permcol(c0), p1 = permcol(c1);
            g_q[b0 + g * 64 + p0] = tfround(v00 * 0.125f);
            g_q[b0 + g * 64 + p1] = tfround(v01 * 0.125f);
            g_q[b1 + g * 64 + p0] = tfround(v10 * 0.125f);
            g_q[b1 + g * 64 + p1] = tfround(v11 * 0.125f);
        } else if (c0 < 128) {
            int p0 = permcol(c0 - 64), p1 = permcol(c1 - 64);
            g_k[b0 + g * 64 + p0] = tfround(v00);
            g_k[b0 + g * 64 + p1] = tfround(v01);
            g_k[b1 + g * 64 + p0] = tfround(v10);
            g_k[b1 + g * 64 + p1] = tfround(v11);
        } else {
            int p0 = c0 - 128, p1 = c1 - 128;
            g_v[b0 + g * 64 + p0] = tfround(v00);
            g_v[b0 + g * 64 + p1] = tfround(v01);
            g_v[b1 + g * 64 + p0] = tfround(v10);
            g_v[b1 + g * 64 + p1] = tfround(v11);
        }
    }
}

// ------------------- K4: flash attention, split-K x8, cp.async, packed LDS.64 -------------------
#define KPAD 72
#define VPAD 72
#define K4_SMEM ((2 * 64 * KPAD + 2 * 64 * VPAD) * 4)

__global__ void __launch_bounds__(128, 3) k4_attn() {
    extern __shared__ float dyn[];
    float* Kbuf[2] = {dyn, dyn + 64 * KPAD};
    float* Vbuf[2] = {dyn + 2 * 64 * KPAD, dyn + 2 * 64 * KPAD + 64 * VPAD};
    int tid = threadIdx.x, lane = tid & 31, warp = tid >> 5;
    int g = lane >> 2, t = lane & 3;
    int view = blockIdx.y;
    int row0 = blockIdx.x * 64;
    int sp = blockIdx.z;
    const int NT = NN / 64 / SPLITS;   // 6
    int kt0 = sp * NT;
    size_t vbase = (size_t)view * NN * 64;

    uint32_t qf[8][4];
    {
        const float* Q = g_q + vbase + (size_t)(row0 + warp * 16) * 64;
        const float2* Qa = (const float2*)(Q + g * 64);
        const float2* Qb = (const float2*)(Q + (g + 8) * 64);
#pragma unroll
        for (int kc = 0; kc < 8; kc++) {
            float2 qa = Qa[kc * 4 + t];
            float2 qb = Qb[kc * 4 + t];
            qf[kc][0] = __float_as_uint(qa.x);
            qf[kc][1] = __float_as_uint(qb.x);
            qf[kc][2] = __float_as_uint(qa.y);
            qf[kc][3] = __float_as_uint(qb.y);
        }
    }
    float m0 = NEGBIG, m1 = NEGBIG, l0 = 0.f, l1 = 0.f;
    float o[8][4];
#pragma unroll
    for (int db = 0; db < 8; db++) { o[db][0] = o[db][1] = o[db][2] = o[db][3] = 0.f; }

    auto load_tile = [&](int kt, int buf) {
        const float* Kg = g_k + vbase + (size_t)kt * 4096;
        const float* Vg = g_v + vbase + (size_t)kt * 4096;
        for (int i = tid; i < 1024; i += 128) {
            int r = i >> 4, c = (i & 15) * 4;
            cp16(&Kbuf[buf][r * KPAD + c], Kg + r * 64 + c);
            cp16(&Vbuf[buf][r * VPAD + c], Vg + r * 64 + c);
        }
        asm volatile("cp.async.commit_group;\n");
    };
    load_tile(kt0, 0);

    for (int it = 0; it < NT; it++) {
        int buf = it & 1;
        __syncthreads();
        if (it + 1 < NT) {
            load_tile(kt0 + it + 1, buf ^ 1);
            asm volatile("cp.async.wait_group 1;\n");
        } else {
            asm volatile("cp.async.wait_group 0;\n");
        }
        __syncthreads();
        float* Ksm = Kbuf[buf];
        float* Vsm = Vbuf[buf];

        float s[8][4];
#pragma unroll
        for (int nb = 0; nb < 8; nb++) { s[nb][0] = s[nb][1] = s[nb][2] = s[nb][3] = 0.f; }
#pragma unroll
        for (int kc = 0; kc < 8; kc++) {
#pragma unroll
            for (int nb = 0; nb < 8; nb++) {
                float2 kv = *(const float2*)&Ksm[(nb * 8 + g) * KPAD + kc * 8 + 2 * t];
                mma_tf32(s[nb], qf[kc], __float_as_uint(kv.x), __float_as_uint(kv.y));
            }
        }
        __syncthreads();

        float tm0 = NEGBIG, tm1 = NEGBIG;
#pragma unroll
        for (int nb = 0; nb < 8; nb++) {
            tm0 = fmaxf(tm0, fmaxf(s[nb][0], s[nb][1]));
            tm1 = fmaxf(tm1, fmaxf(s[nb][2], s[nb][3]));
        }
#pragma unroll
        for (int off = 1; off <= 2; off <<= 1) {
            tm0 = fmaxf(tm0, __shfl_xor_sync(FULLMASK, tm0, off));
            tm1 = fmaxf(tm1, __shfl_xor_sync(FULLMASK, tm1, off));
        }
        float nm0 = fmaxf(m0, tm0), nm1 = fmaxf(m1, tm1);
        float c0 = __expf(m0 - nm0), c1 = __expf(m1 - nm1);
        float r0 = 0.f, r1 = 0.f;
#pragma unroll
        for (int nb = 0; nb < 8; nb++) {
            s[nb][0] = __expf(s[nb][0] - nm0);
            s[nb][1] = __expf(s[nb][1] - nm0);
            s[nb][2] = __expf(s[nb][2] - nm1);
            s[nb][3] = __expf(s[nb][3] - nm1);
            r0 += s[nb][0] + s[nb][1];
            r1 += s[nb][2] + s[nb][3];
        }
#pragma unroll
        for (int off = 1; off <= 2; off <<= 1) {
            r0 += __shfl_xor_sync(FULLMASK, r0, off);
            r1 += __shfl_xor_sync(FULLMASK, r1, off);
        }
        l0 = l0 * c0 + r0;
        l1 = l1 * c1 + r1;
#pragma unroll
        for (int db = 0; db < 8; db++) {
            o[db][0] *= c0; o[db][1] *= c0; o[db][2] *= c1; o[db][3] *= c1;
        }
        m0 = nm0; m1 = nm1;

        float* Pw = Ksm + warp * 16 * KPAD;
        int ps0 = ((2 * t) & 3) * 2 + (t >> 1);
        int ps1 = ((2 * t + 1) & 3) * 2 + (t >> 1);
#pragma unroll
        for (int nb = 0; nb < 8; nb++) {
            Pw[g * KPAD + nb * 8 + ps0]       = tfround(s[nb][0]);
            Pw[g * KPAD + nb * 8 + ps1]       = tfround(s[nb][1]);
            Pw[(g + 8) * KPAD + nb * 8 + ps0] = tfround(s[nb][2]);
            Pw[(g + 8) * KPAD + nb * 8 + ps1] = tfround(s[nb][3]);
        }
        __syncwarp();

#pragma unroll
        for (int kc = 0; kc < 8; kc++) {
            float2 pa = *(const float2*)&Pw[g * KPAD + kc * 8 + 2 * t];
            float2 pb = *(const float2*)&Pw[(g + 8) * KPAD + kc * 8 + 2 * t];
            uint32_t af[4] = {__float_as_uint(pa.x), __float_as_uint(pb.x),
                              __float_as_uint(pa.y), __float_as_uint(pb.y)};
#pragma unroll
            for (int db = 0; db < 8; db++) {
                uint32_t b0 = __float_as_uint(Vsm[(kc * 8 + t) * VPAD + db * 8 + g]);
                uint32_t b1 = __float_as_uint(Vsm[(kc * 8 + t + 4) * VPAD + db * 8 + g]);
                mma_tf32(o[db], af, b0, b1);
            }
        }
    }
    float* P0 = g_po + ((size_t)(sp * VV + view) * NN + row0 + warp * 16) * 64;
#pragma unroll
    for (int db = 0; db < 8; db++) {
        P0[g * 64 + db * 8 + 2 * t]           = o[db][0];
        P0[g * 64 + db * 8 + 2 * t + 1]       = o[db][1];
        P0[(g + 8) * 64 + db * 8 + 2 * t]     = o[db][2];
        P0[(g + 8) * 64 + db * 8 + 2 * t + 1] = o[db][3];
    }
    if (t == 0) {
        int ri = (sp * VV + view) * NN + row0 + warp * 16;
        g_pm[ri + g] = m0;     g_pl[ri + g] = l0;
        g_pm[ri + g + 8] = m1; g_pl[ri + g + 8] = l1;
    }
}

// ------------------- K4c: split-K combine -------------------
__global__ void __launch_bounds__(256) k4c_combine() {
    int tid = threadIdx.x, warp = tid >> 5, lane = tid & 31;
    int gw = blockIdx.x * 8 + warp;
    float ms[SPLITS];
    float M = NEGBIG;
#pragma unroll
    for (int s = 0; s < SPLITS; s++) {
        ms[s] = __ldg(&g_pm[s * (VV * NN) + gw]);
        M = fmaxf(M, ms[s]);
    }
    float c[SPLITS];
    float den = 0.f;
#pragma unroll
    for (int s = 0; s < SPLITS; s++) {
        c[s] = __expf(ms[s] - M);
        den += __ldg(&g_pl[s * (VV * NN) + gw]) * c[s];
    }
    float inv = 1.f / den;
    float n0 = 0.f, n1 = 0.f;
#pragma unroll
    for (int s = 0; s < SPLITS; s++) {
        const float* p = g_po + ((size_t)s * (VV * NN) + gw) * 64;
        n0 += p[lane] * c[s];
        n1 += p[lane + 32] * c[s];
    }
    g_vals[(size_t)gw * 64 + lane]      = n0 * inv;
    g_vals[(size_t)gw * 64 + lane + 32] = n1 * inv;
}

// ------------------- K5: o-proj + fusion -------------------
__global__ void __launch_bounds__(256) k5_fuse(const float* __restrict__ Wo,
                                               const float* __restrict__ bo,
                                               const float* __restrict__ Wf,
                                               const float* __restrict__ bf,
                                               float* __restrict__ out) {
    __shared__ float Wos[64 * 64];
    __shared__ float Wfs[64 * 64];
    int tid = threadIdx.x;
    for (int i = tid; i < 64 * 64; i += 256) { Wos[i] = Wo[i]; Wfs[i] = Wf[i]; }
    __syncthreads();
    int node = blockIdx.x * 8 + (tid >> 5);
    int lane = tid & 31;
    float bo0 = __ldg(bo + lane), bo1 = __ldg(bo + lane + 32);
    float bf0 = __ldg(bf + lane), bf1 = __ldg(bf + lane + 32);
    float fs0 = 0.f, fs1 = 0.f;
    float* vh_out = out + 1024 * 64;
    for (int v = 0; v < VV; v++) {
        const float* vr = g_vals + ((size_t)v * NN + node) * 64;
        float x0 = vr[lane], x1 = vr[lane + 32];
        float o0 = bo0, o1 = bo1;
#pragma unroll
        for (int k = 0; k < 64; k++) {
            float xk = __shfl_sync(FULLMASK, (k < 32) ? x0 : x1, k & 31);
            o0 += xk * Wos[k * 64 + lane];
            o1 += xk * Wos[k * 64 + lane + 32];
        }
        const float* hg = g_hgat + ((size_t)v * NN + node) * 64;
        float hf0 = 0.8f * o0 + 0.2f * hg[lane];
        float hf1 = 0.8f * o1 + 0.2f * hg[lane + 32];
        float w0 = bf0, w1 = bf1;
#pragma unroll
        for (int k = 0; k < 64; k++) {
            float hk = __shfl_sync(FULLMASK, (k < 32) ? hf0 : hf1, k & 31);
            w0 += hk * Wfs[k * 64 + lane];
            w1 += hk * Wfs[k * 64 + lane + 32];
        }
        w0 = 1.f / (1.f + __expf(-w0));
        w1 = 1.f / (1.f + __expf(-w1));
        float hid0 = w0 * hf0, hid1 = w1 * hf1;
        fs0 += hid0; fs1 += hid1;
        float* vh = vh_out + ((size_t)v * NN + node) * 64;
        vh[lane]      = 0.5f * hid0 + 0.5f * hf0;
        vh[lane + 32] = 0.5f * hid1 + 0.5f * hf1;
    }
    if (node >= 2048) {
        float* fo = out + (size_t)(node - 2048) * 64;
        fo[lane] = fs0;
        fo[lane + 32] = fs1;
    }
}

// ------------------- launch -------------------
extern "C" void kernel_launch(void* const* d_in, const int* in_sizes, int n_in,
                              void* d_out, int out_size) {
    const float* adj  = (const float*)d_in[0];
    const float* nf   = (const float*)d_in[1];
    const float* W    = (const float*)d_in[2];
    const float* a    = (const float*)d_in[3];
    const float* Wqkv = (const float*)d_in[4];
    const float* bqkv = (const float*)d_in[5];
    const float* Wo   = (const float*)d_in[6];
    const float* bo   = (const float*)d_in[7];
    const float* Wf   = (const float*)d_in[8];
    const float* bf   = (const float*)d_in[9];
    float* out = (float*)d_out;

    cudaFuncSetAttribute(k3_qkv, cudaFuncAttributeMaxDynamicSharedMemorySize, K3_SMEM);
    cudaFuncSetAttribute(k4_attn, cudaFuncAttributeMaxDynamicSharedMemorySize, K4_SMEM);

    k1_wh<<<NN / 8, 256>>>(nf, W, a);
    k2_gat<<<dim3(NN / 64, VV, JSPLIT), 256>>>(adj);
    k2c_combine<<<VV * NN / 8, 256>>>();
    k3_qkv<<<VV * NN / 64, 128, K3_SMEM>>>(Wqkv, bqkv);
    k4_attn<<<dim3(NN / 64, VV, SPLITS), 128, K4_SMEM>>>();
    k4c_combine<<<VV * NN / 8, 256>>>();
    k5_fuse<<<NN / 8, 256>>>(Wo, bo, Wf, bf, out);
}